// round 16
// baseline (speedup 1.0000x reference)
#include <cuda_runtime.h>
#include <cuda_bf16.h>

#define NCTA 112
#define NTHR 512
#define GT (NCTA * NTHR)
typedef unsigned int u32;

// Weights pre-packed ks-major in mma fragment order, bf16 hi/lo per k-slice:
// unit = 32 slices x [hi 2048][lo 2048] shorts. gates: (l*96+u)*131072 ;
// out: 37748736 + u*131072 (16 units)
__device__ __align__(16) unsigned short g_w[39845888];
__device__ __align__(16) unsigned short g_xt[33554432]; // x B-frags per t
__device__ __align__(16) unsigned short g_bh[3][65536]; // h B-frags per layer
__device__ __align__(16) float g_part[917504];          // [unit][grp][row][b]
__device__ float g_hfp[3][1024][32];                    // fp32 hidden [l][n][b]
__device__ unsigned g_ocnt[8][32], g_ogen[8][32];       // out-pair barriers
__device__ unsigned g_gcnt[14][32];                     // arrival groups of 8
__device__ unsigned g_root = 0, g_gen = 0;

static __device__ __forceinline__ u32 smem_u32(const void* p) {
    u32 a;
    asm("{ .reg .u64 t; cvta.to.shared.u64 t, %1; cvt.u32.u64 %0, t; }" : "=r"(a) : "l"(p));
    return a;
}
static __device__ __forceinline__ unsigned ld_acq(const unsigned* p) {
    unsigned v;
    asm volatile("ld.acquire.gpu.global.u32 %0,[%1];" : "=r"(v) : "l"(p) : "memory");
    return v;
}
static __device__ __forceinline__ unsigned arr_add(unsigned* p) {
    unsigned v;
    asm volatile("atom.acq_rel.gpu.global.add.u32 %0,[%1],1;"
                 : "=r"(v) : "l"(p) : "memory");
    return v;
}
static __device__ __forceinline__ void st_rel(unsigned* p, unsigned v) {
    asm volatile("st.release.gpu.global.u32 [%0],%1;" :: "l"(p), "r"(v) : "memory");
}
static __device__ __forceinline__ void st_rlx(unsigned* p, unsigned v) {
    asm volatile("st.relaxed.gpu.global.u32 [%0],%1;" :: "l"(p), "r"(v) : "memory");
}
// hierarchical grid barrier: 14 groups x 8 arrivals, then root of 14.
static __device__ __forceinline__ void gsync(int cta) {
    __syncthreads();
    if (threadIdx.x == 0) {
        unsigned g;
        asm volatile("ld.relaxed.gpu.global.u32 %0,[%1];" : "=r"(g) : "l"(&g_gen));
        bool rel = false;
        if (arr_add(&g_gcnt[cta >> 3][0]) == 7) {
            st_rlx(&g_gcnt[cta >> 3][0], 0);
            if (arr_add(&g_root) == 13) {
                st_rlx(&g_root, 0);
                st_rel(&g_gen, g + 1);
                rel = true;
            }
        }
        if (!rel) {
            while (ld_acq(&g_gen) == g) { }
        }
    }
    __syncthreads();
}
// small barrier among `num` CTAs (out pairs)
static __device__ __forceinline__ void bsync(unsigned* cnt, unsigned* gen, unsigned num) {
    __syncthreads();
    if (threadIdx.x == 0) {
        unsigned g;
        asm volatile("ld.relaxed.gpu.global.u32 %0,[%1];" : "=r"(g) : "l"(gen));
        if (arr_add(cnt) == num - 1) {
            st_rlx(cnt, 0);
            st_rel(gen, g + 1);
        } else {
            while (ld_acq(gen) == g) { }
        }
    }
    __syncthreads();
}
static __device__ __forceinline__ void hilo(float v, unsigned short& h,
                                            unsigned short& l) {
    __nv_bfloat16 hb = __float2bfloat16(v);
    __nv_bfloat16 lb = __float2bfloat16(v - __bfloat162float(hb));
    h = *(unsigned short*)&hb;
    l = *(unsigned short*)&lb;
}
static __device__ __forceinline__ void mma16816(float* c, uint4 a, u32 b0, u32 b1) {
    asm volatile(
        "mma.sync.aligned.m16n8k16.row.col.f32.bf16.bf16.f32 "
        "{%0,%1,%2,%3}, {%4,%5,%6,%7}, {%8,%9}, {%0,%1,%2,%3};"
        : "+f"(c[0]), "+f"(c[1]), "+f"(c[2]), "+f"(c[3])
        : "r"(a.x), "r"(a.y), "r"(a.z), "r"(a.w), "r"(b0), "r"(b1));
}
static __device__ __forceinline__ int a_idx(int r, int c) {
    int lane = (r & 7) * 4 + ((c & 7) >> 1);
    int j = (r >> 3) + ((c >> 3) << 1);
    return lane * 8 + j * 2 + (c & 1);
}
// Certified conflict-free B layout within 1024-short k-slice:
// hi: (nt>>1)*256 + lane*8 + (nt&1)*4 + s, lo at +512.
static __device__ __forceinline__ int b_inner(int kk, int b) {
    int nt = b >> 3, bn = b & 7;
    int lane = bn * 4 + ((kk & 7) >> 1);
    int s = ((kk >> 3) << 1) + (kk & 1);
    return (nt >> 1) * 256 + lane * 8 + (nt & 1) * 4 + s;
}
static __device__ __forceinline__ void act_store(unsigned short* blk, int k,
                                                 int b, float v) {
    int i = (k >> 4) * 1024 + b_inner(k & 15, b);
    hilo(v, blk[i], blk[i + 512]);
}
static __device__ __forceinline__ void cpa16(u32 dst, const void* src) {
    asm volatile("cp.async.cg.shared.global [%0], [%1], 16;" :: "r"(dst), "l"(src));
}

// [128 x 32 x 512] compensated-bf16 GEMM; two 256-thread groups split K;
// 5-stage cp.async pipeline (A 8KB + B 2KB per 10KB stage).  (R14-proven)
static __device__ void unit_gemm(const unsigned short* __restrict__ wu,
                                 const unsigned short* __restrict__ bs,
                                 float* __restrict__ pdst,
                                 unsigned short* __restrict__ smst) {
    const int tid = threadIdx.x, grp = tid >> 8, ltid = tid & 255;
    const int w = ltid >> 5, lane = ltid & 31;
    unsigned short* st = smst + grp * 25600;  // 5 x 10KB stages
    const u32 smb = smem_u32(st);
    const char* wb = (const char*)wu + grp * 131072;  // 16 slices x 8KB
    const char* bb = (const char*)bs + grp * 32768;   // 16 slices x 2KB

#pragma unroll
    for (int s = 0; s < 4; ++s) {
        for (int c = ltid; c < 640; c += 256) {
            const char* src = (c < 512) ? wb + s * 8192 + c * 16
                                        : bb + s * 2048 + (c - 512) * 16;
            cpa16(smb + s * 10240 + c * 16, src);
        }
        asm volatile("cp.async.commit_group;" ::: "memory");
    }
    float acc[16];
#pragma unroll
    for (int i = 0; i < 16; ++i) acc[i] = 0.f;

#pragma unroll 1
    for (int s = 0; s < 16; ++s) {
        asm volatile("cp.async.wait_group 3;" ::: "memory");
        asm volatile("bar.sync %0, 256;" :: "r"(grp + 1) : "memory");
        const uint4* SA = (const uint4*)(st + (s % 5) * 5120);
        uint4 ah = SA[w * 32 + lane];
        uint4 al = SA[256 + w * 32 + lane];
        const uint4* SB = SA + 512;
        uint4 bh0 = SB[lane], bh1 = SB[32 + lane];
        uint4 bl0 = SB[64 + lane], bl1 = SB[96 + lane];
        mma16816(acc + 0, ah, bh0.x, bh0.y);
        mma16816(acc + 4, ah, bh0.z, bh0.w);
        mma16816(acc + 8, ah, bh1.x, bh1.y);
        mma16816(acc + 12, ah, bh1.z, bh1.w);
        mma16816(acc + 0, ah, bl0.x, bl0.y);
        mma16816(acc + 4, ah, bl0.z, bl0.w);
        mma16816(acc + 8, ah, bl1.x, bl1.y);
        mma16816(acc + 12, ah, bl1.z, bl1.w);
        mma16816(acc + 0, al, bh0.x, bh0.y);
        mma16816(acc + 4, al, bh0.z, bh0.w);
        mma16816(acc + 8, al, bh1.x, bh1.y);
        mma16816(acc + 12, al, bh1.z, bh1.w);
        const int nk = s + 4;
        if (nk < 16) {
            const int ns = nk % 5;
            for (int c = ltid; c < 640; c += 256) {
                const char* src = (c < 512) ? wb + nk * 8192 + c * 16
                                            : bb + nk * 2048 + (c - 512) * 16;
                cpa16(smb + ns * 10240 + c * 16, src);
            }
        }
        asm volatile("cp.async.commit_group;" ::: "memory");
    }
    float* pd = pdst + grp * 4096;
    const int r0 = w * 16 + (lane >> 2), cb = (lane & 3) * 2;
#pragma unroll
    for (int nt = 0; nt < 4; ++nt) {
        *(float2*)(pd + r0 * 32 + nt * 8 + cb) =
            make_float2(acc[nt * 4], acc[nt * 4 + 1]);
        *(float2*)(pd + (r0 + 8) * 32 + nt * 8 + cb) =
            make_float2(acc[nt * 4 + 2], acc[nt * 4 + 3]);
    }
}

__global__ void __launch_bounds__(NTHR, 1)
gru_tc(const float* __restrict__ x, const float* __restrict__ h0,
       const float* __restrict__ Wzi, const float* __restrict__ Wzh,
       const float* __restrict__ bzh, const float* __restrict__ Wri,
       const float* __restrict__ Wrh, const float* __restrict__ brh,
       const float* __restrict__ Wgi, const float* __restrict__ Wgh,
       const float* __restrict__ bgh, const float* __restrict__ Wout,
       const float* __restrict__ bout, float* __restrict__ out) {
    extern __shared__ __align__(16) unsigned short smst[];  // 2 x 50KB
    const int tid = threadIdx.x, cta = blockIdx.x, gtid = cta * NTHR + tid;

    // ---- init: pack weights ks-major fragment order (hi/lo) ----
    const float* gm[6] = {Wzi, Wzh, Wri, Wrh, Wgi, Wgh};
    for (long e = gtid; e < 18874368L; e += GT) {
        int m = (int)(e / 3145728);
        long rem = e - (long)m * 3145728;
        int l = (int)(rem >> 20), j = (int)(rem & 1048575);
        int n = j >> 10, k = j & 1023;
        int u = (n >> 7) * 12 + m * 2 + (k >> 9);
        int k5 = k & 511, ww = (n >> 4) & 7;
        long base = ((long)l * 96 + u) * 131072;
        int idx = (k5 >> 4) * 4096 + ww * 256 + a_idx(n & 15, k5 & 15);
        hilo(gm[m][(long)l * 1048576 + j], g_w[base + idx], g_w[base + idx + 2048]);
    }
    for (long e = gtid; e < 1048576L; e += GT) {
        int n = (int)(e >> 10), k = (int)(e & 1023);
        int u = (n >> 7) * 2 + (k >> 9);
        int k5 = k & 511, ww = (n >> 4) & 7;
        long base = 37748736L + (long)u * 131072;
        int idx = (k5 >> 4) * 4096 + ww * 256 + a_idx(n & 15, k5 & 15);
        hilo(Wout[e], g_w[base + idx], g_w[base + idx + 2048]);
    }
    for (long e = gtid; e < 16777216L; e += GT) {
        int b = (int)(e >> 19), t = (int)((e >> 10) & 511), k = (int)(e & 1023);
        act_store(g_xt + (long)t * 65536 + (k >> 9) * 32768, k & 511, b, x[e]);
    }
    for (int e = gtid; e < 98304; e += GT) {
        int l = e / 32768, i = e & 32767, b = i >> 10, h = i & 1023;
        float v = h0[((long)b * 3 + l) * 1024 + h];
        g_hfp[l][h][b] = v;
        act_store(&g_bh[l][(h >> 9) * 32768], h & 511, b, v);
    }
    gsync(cta);

    const int oj = (cta - 96) >> 1, oh = (cta - 96) & 1;  // out pairs

#pragma unroll 1
    for (int t = 0; t < 512; ++t) {
#pragma unroll 1
        for (int l = 0; l < 3; ++l) {
            // ---- gemm phase ----
            if (cta < 96) {
                int sub = cta % 12, m = sub >> 1, kh = sub & 1;
                const unsigned short* bs =
                    (m & 1) ? g_bh[l] : (l == 0 ? g_xt + (long)t * 65536 : g_bh[l - 1]);
                unit_gemm(g_w + ((long)l * 96 + cta) * 131072, bs + kh * 32768,
                          g_part + (long)cta * 8192, smst);
            } else if (l == 0 && t > 0) {
                unit_gemm(g_w + 37748736L + (long)(cta - 96) * 131072,
                          g_bh[2] + oh * 32768, g_part + (long)cta * 8192, smst);
            }
            gsync(cta);
            // ---- combine phase (grid-wide, globally fenced both sides) ----
            for (int i = gtid; i < 32768; i += GT) {
                int n = i >> 5, b = i & 31, blk = n >> 7, nl = n & 127;
                const float* P = g_part + (long)blk * 98304 + nl * 32 + b;
                float zs = 0.f, rs = 0.f, gi = 0.f, gh = 0.f;
#pragma unroll
                for (int j = 0; j < 8; ++j) zs += P[j * 4096];
#pragma unroll
                for (int j = 8; j < 16; ++j) rs += P[j * 4096];
#pragma unroll
                for (int j = 16; j < 20; ++j) gi += P[j * 4096];
#pragma unroll
                for (int j = 20; j < 24; ++j) gh += P[j * 4096];
                float z = 1.f / (1.f + expf(-(zs + bzh[l * 1024 + n])));
                float r = 1.f / (1.f + expf(-(rs + brh[l * 1024 + n])));
                float g = tanhf(gi + r * (gh + bgh[l * 1024 + n]));
                float hn = z * g_hfp[l][n][b] + (1.f - z) * g;
                g_hfp[l][n][b] = hn;
                act_store(&g_bh[l][(n >> 9) * 32768], n & 511, b, hn);
            }
            if (l == 0 && t > 0) {
                for (int i = gtid; i < 32768; i += GT) {
                    int n = i >> 5, b = i & 31, nb = n >> 7, nl = n & 127;
                    const float* P = g_part + (long)(192 + nb * 4) * 4096 + nl * 32 + b;
                    out[((long)b * 512 + (t - 1)) * 1024 + n] =
                        P[0] + P[4096] + P[8192] + P[12288] + bout[n];
                }
            }
            gsync(cta);
        }
    }
    // epilogue: final out-proj (t=511) + final hidden state
    if (cta >= 96) {
        unit_gemm(g_w + 37748736L + (long)(cta - 96) * 131072,
                  g_bh[2] + oh * 32768, g_part + (long)cta * 8192, smst);
        bsync(&g_ocnt[oj][0], &g_ogen[oj][0], 2);
        const float* Pb = g_part + (long)(96 + oj * 2) * 8192;
        for (int i = oh * NTHR + tid; i < 4096; i += 2 * NTHR) {
            int nl = i >> 5, b = i & 31, n = oj * 128 + nl;
            const float* P = Pb + nl * 32 + b;
            out[((long)b * 512 + 511) * 1024 + n] =
                P[0] + P[4096] + P[8192] + P[12288] + bout[n];
        }
    } else {
        for (int e = cta * NTHR + tid; e < 98304; e += 96 * NTHR) {
            int l = e / 32768, i = e & 32767, b = i >> 10, h = i & 1023;
            out[16777216L + ((long)b * 3 + l) * 1024 + h] = g_hfp[l][h][b];
        }
    }
}

extern "C" void kernel_launch(void* const* d_in, const int* in_sizes, int n_in,
                              void* d_out, int out_size) {
    const int smem = 2 * 5 * 10240;  // 100KB
    cudaFuncSetAttribute(gru_tc, cudaFuncAttributeMaxDynamicSharedMemorySize, smem);
    gru_tc<<<NCTA, NTHR, smem>>>(
        (const float*)d_in[0], (const float*)d_in[1], (const float*)d_in[2],
        (const float*)d_in[3], (const float*)d_in[4], (const float*)d_in[5],
        (const float*)d_in[6], (const float*)d_in[7], (const float*)d_in[8],
        (const float*)d_in[9], (const float*)d_in[10], (const float*)d_in[11],
        (const float*)d_in[12], (float*)d_out);
}

// round 17
// speedup vs baseline: 1.1753x; 1.1753x over previous
#include <cuda_runtime.h>
#include <cuda_bf16.h>

#define NCTA 112
#define NTHR 512
#define GT (NCTA * NTHR)
typedef unsigned int u32;

// Weights pre-packed in tf32 m16n8k8 fragment order, iter-major:
// unit = 65536 u32 (2 groups x 16 iters x [subA0 1024][subA1 1024]).
// gates: (l*96+u)*65536 ; out: 18874368 + u*65536 (16 units)
__device__ __align__(16) u32 g_w[19922944];
__device__ __align__(16) u32 g_xt[16777216];   // x B-frags per t (32768 u32)
__device__ __align__(16) u32 g_bh[3][32768];   // h B-frags per layer
__device__ __align__(16) float g_part[917504]; // [unit][grp][row][b]
__device__ float g_hfp[3][1024][32];           // fp32 hidden [l][n][b]
__device__ unsigned g_ocnt[8][32], g_ogen[8][32];
__device__ unsigned g_cnt = 0, g_gen = 0;

static __device__ __forceinline__ u32 smem_u32(const void* p) {
    u32 a;
    asm("{ .reg .u64 t; cvta.to.shared.u64 t, %1; cvt.u32.u64 %0, t; }" : "=r"(a) : "l"(p));
    return a;
}
static __device__ __forceinline__ u32 tf32b(float v) {
    u32 r;
    asm("cvt.rna.tf32.f32 %0, %1;" : "=r"(r) : "f"(v));
    return r;
}
static __device__ __forceinline__ unsigned ld_acq(const unsigned* p) {
    unsigned v;
    asm volatile("ld.acquire.gpu.global.u32 %0,[%1];" : "=r"(v) : "l"(p) : "memory");
    return v;
}
static __device__ __forceinline__ unsigned arr_add(unsigned* p) {
    unsigned v;
    asm volatile("atom.acq_rel.gpu.global.add.u32 %0,[%1],1;"
                 : "=r"(v) : "l"(p) : "memory");
    return v;
}
static __device__ __forceinline__ void st_rel(unsigned* p, unsigned v) {
    asm volatile("st.release.gpu.global.u32 [%0],%1;" :: "l"(p), "r"(v) : "memory");
}
static __device__ __forceinline__ void st_rlx(unsigned* p, unsigned v) {
    asm volatile("st.relaxed.gpu.global.u32 [%0],%1;" :: "l"(p), "r"(v) : "memory");
}
// R14-proven barrier (single counter, nanosleep backoff)
static __device__ __forceinline__ void bsync(unsigned* cnt, unsigned* gen, unsigned num) {
    __syncthreads();
    if (threadIdx.x == 0) {
        unsigned g;
        asm volatile("ld.relaxed.gpu.global.u32 %0,[%1];" : "=r"(g) : "l"(gen));
        if (arr_add(cnt) == num - 1) {
            st_rlx(cnt, 0);
            st_rel(gen, g + 1);
        } else {
            unsigned cur;
            do {
                __nanosleep(64);
                cur = ld_acq(gen);
            } while (cur == g);
        }
    }
    __syncthreads();
}
static __device__ __forceinline__ void mma_tf32(float* c, uint4 a, u32 b0, u32 b1) {
    asm volatile(
        "mma.sync.aligned.m16n8k8.row.col.f32.tf32.tf32.f32 "
        "{%0,%1,%2,%3}, {%4,%5,%6,%7}, {%8,%9}, {%0,%1,%2,%3};"
        : "+f"(c[0]), "+f"(c[1]), "+f"(c[2]), "+f"(c[3])
        : "r"(a.x), "r"(a.y), "r"(a.z), "r"(a.w), "r"(b0), "r"(b1));
}
// B activation store (tf32 fragment order), k in 0..511 within khalf block
static __device__ __forceinline__ void act_store(u32* blk, int k, int b, float v) {
    int g = k >> 8, ii = (k >> 4) & 15, ss = (k >> 3) & 1, kk = k & 7;
    int nt = b >> 3, bn = b & 7;
    int idx = g * 8192 + (ii * 2 + ss) * 256 + (nt >> 1) * 128 +
              (bn * 4 + (kk & 3)) * 4 + (nt & 1) * 2 + (kk >> 2);
    blk[idx] = tf32b(v);
}
static __device__ __forceinline__ void cpa16(u32 dst, const void* src) {
    asm volatile("cp.async.cg.shared.global [%0], [%1], 16;" :: "r"(dst), "l"(src));
}

// [128 x 32 x 512] tf32 GEMM; two 256-thread groups split K;
// 5-stage cp.async pipeline (A 8KB + B 2KB per 10KB stage; same bytes as R14).
static __device__ void unit_gemm(const u32* __restrict__ wu,
                                 const u32* __restrict__ bs,
                                 float* __restrict__ pdst,
                                 u32* __restrict__ smst) {
    const int tid = threadIdx.x, grp = tid >> 8, ltid = tid & 255;
    const int w = ltid >> 5, lane = ltid & 31;
    u32* st = smst + grp * 12800;  // 5 x 2560 u32 stages (10KB each)
    const u32 smb = smem_u32(st);
    const char* wb = (const char*)wu + grp * 131072;  // 16 iters x 8KB
    const char* bb = (const char*)bs + grp * 32768;   // 16 iters x 2KB

#pragma unroll
    for (int s = 0; s < 4; ++s) {
        for (int c = ltid; c < 640; c += 256) {
            const char* src = (c < 512) ? wb + s * 8192 + c * 16
                                        : bb + s * 2048 + (c - 512) * 16;
            cpa16(smb + s * 10240 + c * 16, src);
        }
        asm volatile("cp.async.commit_group;" ::: "memory");
    }
    float acc[16];
#pragma unroll
    for (int i = 0; i < 16; ++i) acc[i] = 0.f;

#pragma unroll 1
    for (int s = 0; s < 16; ++s) {
        asm volatile("cp.async.wait_group 3;" ::: "memory");
        asm volatile("bar.sync %0, 256;" :: "r"(grp + 1) : "memory");
        const uint4* SA = (const uint4*)(st + (s % 5) * 2560);
        const uint4* SB = SA + 512;  // B after 2048 floats of A
#pragma unroll
        for (int sb = 0; sb < 2; ++sb) {
            uint4 a = SA[sb * 256 + w * 32 + lane];
            uint4 bp0 = SB[sb * 64 + lane];
            uint4 bp1 = SB[sb * 64 + 32 + lane];
            mma_tf32(acc + 0, a, bp0.x, bp0.y);
            mma_tf32(acc + 4, a, bp0.z, bp0.w);
            mma_tf32(acc + 8, a, bp1.x, bp1.y);
            mma_tf32(acc + 12, a, bp1.z, bp1.w);
        }
        const int nk = s + 4;
        if (nk < 16) {
            const int ns = nk % 5;
            for (int c = ltid; c < 640; c += 256) {
                const char* src = (c < 512) ? wb + nk * 8192 + c * 16
                                            : bb + nk * 2048 + (c - 512) * 16;
                cpa16(smb + ns * 10240 + c * 16, src);
            }
        }
        asm volatile("cp.async.commit_group;" ::: "memory");
    }
    float* pd = pdst + grp * 4096;
    const int r0 = w * 16 + (lane >> 2), cb = (lane & 3) * 2;
#pragma unroll
    for (int nt = 0; nt < 4; ++nt) {
        *(float2*)(pd + r0 * 32 + nt * 8 + cb) =
            make_float2(acc[nt * 4], acc[nt * 4 + 1]);
        *(float2*)(pd + (r0 + 8) * 32 + nt * 8 + cb) =
            make_float2(acc[nt * 4 + 2], acc[nt * 4 + 3]);
    }
}

__global__ void __launch_bounds__(NTHR, 1)
gru_tc(const float* __restrict__ x, const float* __restrict__ h0,
       const float* __restrict__ Wzi, const float* __restrict__ Wzh,
       const float* __restrict__ bzh, const float* __restrict__ Wri,
       const float* __restrict__ Wrh, const float* __restrict__ brh,
       const float* __restrict__ Wgi, const float* __restrict__ Wgh,
       const float* __restrict__ bgh, const float* __restrict__ Wout,
       const float* __restrict__ bout, float* __restrict__ out) {
    extern __shared__ __align__(16) u32 smst[];  // 2 x 50KB
    const int tid = threadIdx.x, cta = blockIdx.x, gtid = cta * NTHR + tid;

    // ---- init: pack weights into tf32 fragment order ----
    const float* gm[6] = {Wzi, Wzh, Wri, Wrh, Wgi, Wgh};
    for (long e = gtid; e < 18874368L; e += GT) {
        int m = (int)(e / 3145728);
        long rem = e - (long)m * 3145728;
        int l = (int)(rem >> 20), j = (int)(rem & 1048575);
        int n = j >> 10, k = j & 1023;
        int u = (n >> 7) * 12 + m * 2 + (k >> 9);
        int k5 = k & 511, nl = n & 127;
        int g = k5 >> 8, ii = (k5 >> 4) & 15, ss = (k5 >> 3) & 1, kk = k5 & 7;
        int ww = nl >> 4, r16 = nl & 15;
        int lane = (r16 & 7) * 4 + (kk & 3);
        int fj = (r16 >> 3) + ((kk >> 2) << 1);
        int idx = ((g * 16 + ii) * 2 + ss) * 1024 + ww * 128 + lane * 4 + fj;
        g_w[((long)(l * 96 + u)) * 65536 + idx] = tf32b(gm[m][(long)l * 1048576 + j]);
    }
    for (long e = gtid; e < 1048576L; e += GT) {
        int n = (int)(e >> 10), k = (int)(e & 1023);
        int u = (n >> 7) * 2 + (k >> 9);
        int k5 = k & 511, nl = n & 127;
        int g = k5 >> 8, ii = (k5 >> 4) & 15, ss = (k5 >> 3) & 1, kk = k5 & 7;
        int ww = nl >> 4, r16 = nl & 15;
        int lane = (r16 & 7) * 4 + (kk & 3);
        int fj = (r16 >> 3) + ((kk >> 2) << 1);
        int idx = ((g * 16 + ii) * 2 + ss) * 1024 + ww * 128 + lane * 4 + fj;
        g_w[18874368L + (long)u * 65536 + idx] = tf32b(Wout[e]);
    }
    for (long e = gtid; e < 16777216L; e += GT) {
        int b = (int)(e >> 19), t = (int)((e >> 10) & 511), k = (int)(e & 1023);
        act_store(g_xt + (long)t * 32768 + (k >> 9) * 16384, k & 511, b, x[e]);
    }
    for (int e = gtid; e < 98304; e += GT) {
        int l = e / 32768, i = e & 32767, b = i >> 10, h = i & 1023;
        float v = h0[((long)b * 3 + l) * 1024 + h];
        g_hfp[l][h][b] = v;
        act_store(&g_bh[l][(h >> 9) * 16384], h & 511, b, v);
    }
    bsync(&g_cnt, &g_gen, NCTA);

    const int oj = (cta - 96) >> 1, oh = (cta - 96) & 1;  // out pairs

#pragma unroll 1
    for (int t = 0; t < 512; ++t) {
#pragma unroll 1
        for (int l = 0; l < 3; ++l) {
            // ---- gemm phase ----
            if (cta < 96) {
                int sub = cta % 12, m = sub >> 1, kh = sub & 1;
                const u32* bs =
                    (m & 1) ? g_bh[l] : (l == 0 ? g_xt + (long)t * 32768 : g_bh[l - 1]);
                unit_gemm(g_w + ((long)(l * 96 + cta)) * 65536, bs + kh * 16384,
                          g_part + (long)cta * 8192, smst);
            } else if (l == 0 && t > 0) {
                unit_gemm(g_w + 18874368L + (long)(cta - 96) * 65536,
                          g_bh[2] + oh * 16384, g_part + (long)cta * 8192, smst);
            }
            bsync(&g_cnt, &g_gen, NCTA);
            // ---- combine phase (grid-wide, globally fenced both sides) ----
            for (int i = gtid; i < 32768; i += GT) {
                int n = i >> 5, b = i & 31, blk = n >> 7, nl = n & 127;
                const float* P = g_part + (long)blk * 98304 + nl * 32 + b;
                float zs = 0.f, rs = 0.f, gi = 0.f, gh = 0.f;
#pragma unroll
                for (int j = 0; j < 8; ++j) zs += P[j * 4096];
#pragma unroll
                for (int j = 8; j < 16; ++j) rs += P[j * 4096];
#pragma unroll
                for (int j = 16; j < 20; ++j) gi += P[j * 4096];
#pragma unroll
                for (int j = 20; j < 24; ++j) gh += P[j * 4096];
                float z = 1.f / (1.f + expf(-(zs + bzh[l * 1024 + n])));
                float r = 1.f / (1.f + expf(-(rs + brh[l * 1024 + n])));
                float g = tanhf(gi + r * (gh + bgh[l * 1024 + n]));
                float hn = z * g_hfp[l][n][b] + (1.f - z) * g;
                g_hfp[l][n][b] = hn;
                act_store(&g_bh[l][(n >> 9) * 16384], n & 511, b, hn);
            }
            if (l == 0 && t > 0) {
                for (int i = gtid; i < 32768; i += GT) {
                    int n = i >> 5, b = i & 31, nb = n >> 7, nl = n & 127;
                    const float* P = g_part + (long)(192 + nb * 4) * 4096 + nl * 32 + b;
                    out[((long)b * 512 + (t - 1)) * 1024 + n] =
                        P[0] + P[4096] + P[8192] + P[12288] + bout[n];
                }
            }
            bsync(&g_cnt, &g_gen, NCTA);
        }
    }
    // epilogue: final out-proj (t=511) + final hidden state
    if (cta >= 96) {
        unit_gemm(g_w + 18874368L + (long)(cta - 96) * 65536,
                  g_bh[2] + oh * 16384, g_part + (long)cta * 8192, smst);
        bsync(&g_ocnt[oj][0], &g_ogen[oj][0], 2);
        const float* Pb = g_part + (long)(96 + oj * 2) * 8192;
        for (int i = oh * NTHR + tid; i < 4096; i += 2 * NTHR) {
            int nl = i >> 5, b = i & 31, n = oj * 128 + nl;
            const float* P = Pb + nl * 32 + b;
            out[((long)b * 512 + 511) * 1024 + n] =
                P[0] + P[4096] + P[8192] + P[12288] + bout[n];
        }
    } else {
        for (int e = cta * NTHR + tid; e < 98304; e += 96 * NTHR) {
            int l = e / 32768, i = e & 32767, b = i >> 10, h = i & 1023;
            out[16777216L + ((long)b * 3 + l) * 1024 + h] = g_hfp[l][h][b];
        }
    }
}

extern "C" void kernel_launch(void* const* d_in, const int* in_sizes, int n_in,
                              void* d_out, int out_size) {
    const int smem = 2 * 5 * 10240;  // 100KB
    cudaFuncSetAttribute(gru_tc, cudaFuncAttributeMaxDynamicSharedMemorySize, smem);
    gru_tc<<<NCTA, NTHR, smem>>>(
        (const float*)d_in[0], (const float*)d_in[1], (const float*)d_in[2],
        (const float*)d_in[3], (const float*)d_in[4], (const float*)d_in[5],
        (const float*)d_in[6], (const float*)d_in[7], (const float*)d_in[8],
        (const float*)d_in[9], (const float*)d_in[10], (const float*)d_in[11],
        (const float*)d_in[12], (float*)d_out);
}